// round 4
// baseline (speedup 1.0000x reference)
#include <cuda_runtime.h>
#include <cuda_bf16.h>
#include <cstdint>

// SegmentSum: x[600000,128] f32, sorted index -> out[50000,128] f32
// R2 ownership (no atomics/memset) + R3 decoupled loads + R4 software
// pipeline: double-buffered batches of 4 rows so loads for batch i+1 are in
// flight while batch i's register-only run logic executes (sustained MLP).

#define D_FEAT 128
#define ROWS_PER_WARP 64
#define U 4
#define THREADS_PER_BLOCK 128
#define FULL 0xffffffffu

__device__ __forceinline__ void store_seg(float* __restrict__ out, int seg,
                                          float4 a, int lane) {
    reinterpret_cast<float4*>(out)[(size_t)seg * 32 + lane] = a;
}

__device__ __forceinline__ void zero_range(float* __restrict__ out, int s0,
                                           int s1, int lane) {
    const float4 z = make_float4(0.f, 0.f, 0.f, 0.f);
    for (int s = s0; s < s1; ++s)
        reinterpret_cast<float4*>(out)[(size_t)s * 32 + lane] = z;
}

struct Batch {
    int id[U];
    float4 v[U];
    int n;
};

__device__ __forceinline__ void load_batch(const int* __restrict__ index,
                                           const float4* __restrict__ xv,
                                           long r, long end, int lane,
                                           Batch& b) {
    int nb = (int)(end - r);
    if (nb > U) nb = U;
    if (nb < 0) nb = 0;
    b.n = nb;
    #pragma unroll
    for (int i = 0; i < U; ++i) {
        if (i < nb) {
            b.id[i] = __ldg(&index[r + i]);
            b.v[i] = xv[(r + i) * 32 + lane];
        }
    }
}

__device__ __forceinline__ void process_batch(float* __restrict__ out, int lane,
                                              const Batch& b, int& cur,
                                              float4& acc) {
    #pragma unroll
    for (int i = 0; i < U; ++i) {
        if (i < b.n) {
            if (b.id[i] != cur) {
                store_seg(out, cur, acc, lane);
                zero_range(out, cur + 1, b.id[i], lane);
                cur = b.id[i];
                acc = make_float4(0.f, 0.f, 0.f, 0.f);
            }
            acc.x += b.v[i].x;
            acc.y += b.v[i].y;
            acc.z += b.v[i].z;
            acc.w += b.v[i].w;
        }
    }
}

__global__ void __launch_bounds__(THREADS_PER_BLOCK, 8)
segment_sum_kernel(const float* __restrict__ x,
                   const int* __restrict__ index,
                   float* __restrict__ out,
                   int n_rows, int n_seg) {
    const int warp_global = (blockIdx.x * blockDim.x + threadIdx.x) >> 5;
    const int lane = threadIdx.x & 31;

    long start = (long)warp_global * ROWS_PER_WARP;
    if (start >= n_rows) return;
    long end = start + ROWS_PER_WARP;
    if (end > n_rows) end = n_rows;

    const float4* __restrict__ xv = reinterpret_cast<const float4*>(x);

    long r = start;
    if (start > 0) {
        // Warp-parallel skip of the continuation run (owned by earlier warp).
        const int prev = __ldg(&index[start - 1]);
        for (;;) {
            long rr = r + lane;
            int iv = (rr < n_rows) ? __ldg(&index[rr]) : prev + 1;
            unsigned diff = __ballot_sync(FULL, iv != prev);
            if (diff) { r += __ffs(diff) - 1; break; }
            r += 32;
            if (r >= end) return;  // whole chunk is a continuation
        }
        if (r >= end) return;
    } else {
        zero_range(out, 0, __ldg(&index[0]), lane);
    }

    int cur = __ldg(&index[r]);
    float4 acc = make_float4(0.f, 0.f, 0.f, 0.f);

    // ---- Pipelined main loop over owned rows in [r, end) ----
    Batch A, B;
    load_batch(index, xv, r, end, lane, A);
    while (A.n > 0) {
        load_batch(index, xv, r + A.n, end, lane, B);   // prefetch
        process_batch(out, lane, A, cur, acc);
        r += A.n;
        if (B.n == 0) break;
        load_batch(index, xv, r + B.n, end, lane, A);   // prefetch
        process_batch(out, lane, B, cur, acc);
        r += B.n;
    }

    // ---- Spill: current run (owned) may continue past chunk end ----
    for (;;) {
        if (r >= n_rows) {  // globally last segment: store + zero tail
            store_seg(out, cur, acc, lane);
            zero_range(out, cur + 1, n_seg, lane);
            return;
        }
        long rr = r + lane;
        int iv = (rr < n_rows) ? __ldg(&index[rr]) : cur + 1;
        unsigned diff = __ballot_sync(FULL, iv != cur);
        int k = diff ? (__ffs(diff) - 1) : 32;  // rows r..r+k-1 belong to cur
        #pragma unroll 8
        for (int i = 0; i < k; ++i) {
            float4 t = xv[(r + i) * 32 + lane];
            acc.x += t.x;
            acc.y += t.y;
            acc.z += t.z;
            acc.w += t.w;
        }
        r += k;
        if (r >= n_rows) {
            store_seg(out, cur, acc, lane);
            zero_range(out, cur + 1, n_seg, lane);
            return;
        }
        if (k < 32) {  // transition at row r; next segment owned later
            int nxt = __shfl_sync(FULL, iv, k);
            store_seg(out, cur, acc, lane);
            zero_range(out, cur + 1, nxt, lane);
            return;
        }
    }
}

extern "C" void kernel_launch(void* const* d_in, const int* in_sizes, int n_in,
                              void* d_out, int out_size) {
    const float* x = (const float*)d_in[0];
    const int* index = (const int*)d_in[1];
    float* out = (float*)d_out;

    const int n_rows = in_sizes[1];
    const int n_seg = out_size / D_FEAT;

    const int n_warps = (n_rows + ROWS_PER_WARP - 1) / ROWS_PER_WARP;
    const int warps_per_block = THREADS_PER_BLOCK / 32;
    const int n_blocks = (n_warps + warps_per_block - 1) / warps_per_block;
    segment_sum_kernel<<<n_blocks, THREADS_PER_BLOCK>>>(x, index, out,
                                                        n_rows, n_seg);
}